// round 4
// baseline (speedup 1.0000x reference)
#include <cuda_runtime.h>
#include <cuda_bf16.h>

#define NN 100000
#define INC 64
#define HIDC 128
#define OUTC 64
#define NCLS 20

// ---------------- device scratch (static globals; no allocation) ------------
__device__ int   g_is64;
__device__ float g_deg[NN];
__device__ float g_dinv[NN];
__device__ __align__(16) float g_agg1[(size_t)NN * INC];
__device__ __align__(16) float g_h1[(size_t)NN * HIDC];
__device__ __align__(16) float g_p[(size_t)NN * OUTC];
__device__ __align__(16) float g_aggp[(size_t)NN * OUTC];
__device__ __align__(16) float g_h2[(size_t)NN * OUTC];  // s2 then h2 in-place

// Edge index accessor: handles int32 or int64 storage, selected by flag.
__device__ __forceinline__ int edge_idx(const void* ei, long long pos, int is64) {
    if (is64) return (int)((const long long*)ei)[pos];
    return ((const int*)ei)[pos];
}

// ---------------- kernels ---------------------------------------------------

// Detect edge dtype: if data is int64 (values < 2^31), every odd int32 word is 0.
__global__ void k_detect(const int* __restrict__ ei32, int n32, int* __restrict__ flag) {
    __shared__ int s_any;
    if (threadIdx.x == 0) s_any = 0;
    __syncthreads();
    int nonzero = 0;
    int limit = n32 < 16384 ? n32 : 16384;
    for (int i = 1 + 2 * threadIdx.x; i < limit; i += 2 * blockDim.x)
        if (ei32[i] != 0) nonzero = 1;
    if (nonzero) atomicOr(&s_any, 1);
    __syncthreads();
    if (threadIdx.x == 0) *flag = (s_any == 0) ? 1 : 0;  // all-zero odd words -> int64
}

// zero-fill scratch (graph-capturable; no memset nodes on symbol memory)
__global__ void k_zero(float4* __restrict__ a, long long na4,
                       float4* __restrict__ b, long long nb4,
                       float* __restrict__ c, int nc) {
    long long i = (long long)blockIdx.x * blockDim.x + threadIdx.x;
    const float4 z = make_float4(0.f, 0.f, 0.f, 0.f);
    if (i < na4) a[i] = z;
    if (i < nb4) b[i] = z;
    if (i < nc) c[i] = 0.f;
}

// degree: one thread per edge
__global__ void k_deg(const void* __restrict__ ei, int nE, float* __restrict__ deg,
                      const int* __restrict__ flag) {
    int e = blockIdx.x * blockDim.x + threadIdx.x;
    if (e < nE) {
        int d = edge_idx(ei, (long long)nE + e, *flag);
        if ((unsigned)d < NN) atomicAdd(&deg[d], 1.0f);
    }
}

__global__ void k_deginv(const float* __restrict__ deg, float* __restrict__ dinv) {
    int i = blockIdx.x * blockDim.x + threadIdx.x;
    if (i < NN) dinv[i] = 1.0f / fmaxf(deg[i], 1.0f);
}

// segment-sum of a 64-wide feature table along edges: 16 threads/edge.
// float4 gather + 4 scalar atomicAdd (unused return -> REDG, no round-trip).
__global__ void k_agg64(const float4* __restrict__ feat, const void* __restrict__ ei,
                        int nE, float* __restrict__ agg, const int* __restrict__ flag) {
    long long idx = (long long)blockIdx.x * blockDim.x + threadIdx.x;
    long long total = (long long)nE * 16;
    if (idx >= total) return;
    int is64 = *flag;
    int e = (int)(idx >> 4);
    int c = (int)(idx & 15);
    int s = edge_idx(ei, e, is64);
    int d = edge_idx(ei, (long long)nE + e, is64);
    if ((unsigned)s >= NN || (unsigned)d >= NN) return;
    float4 v = __ldg(&feat[(long long)s * 16 + c]);
    float* a = agg + (long long)d * 64 + c * 4;
    atomicAdd(a + 0, v.x);
    atomicAdd(a + 1, v.y);
    atomicAdd(a + 2, v.z);
    atomicAdd(a + 3, v.w);
}

// layer1: h1[n][j] = relu( sum_k x[n][k]*Ws[k][j] + (agg1[n][k]*dinv[n])*Wn[k][j] + b[j] )
// blockDim=128 (j = output col), 32 nodes per block, two weight passes (smem <= 48KB)
__global__ __launch_bounds__(128) void k_layer1(
    const float* __restrict__ x, const float* __restrict__ agg,
    const float* __restrict__ dinv,
    const float* __restrict__ Wself, const float* __restrict__ Wneigh,
    const float* __restrict__ b, float* __restrict__ h1) {
    __shared__ float sW[INC * HIDC];   // 32 KB
    __shared__ float sF[32 * INC];     // 8 KB
    __shared__ float sD[32];
    const int j = threadIdx.x;
    const int n0 = blockIdx.x * 32;
    float acc[32];
#pragma unroll
    for (int n = 0; n < 32; n++) acc[n] = 0.0f;

    if (j < 32) sD[j] = dinv[n0 + j];
    for (int i = j; i < INC * HIDC; i += 128) sW[i] = Wself[i];
    {
        const float* xr = x + (long long)n0 * INC;
        for (int i = j; i < 32 * INC; i += 128) sF[i] = xr[i];
    }
    __syncthreads();
#pragma unroll 4
    for (int k = 0; k < INC; k++) {
        float w = sW[k * HIDC + j];
#pragma unroll
        for (int n = 0; n < 32; n++) acc[n] = fmaf(sF[n * INC + k], w, acc[n]);
    }
    __syncthreads();
    for (int i = j; i < INC * HIDC; i += 128) sW[i] = Wneigh[i];
    {
        const float* ar = agg + (long long)n0 * INC;
        for (int i = j; i < 32 * INC; i += 128) sF[i] = ar[i] * sD[i >> 6];
    }
    __syncthreads();
#pragma unroll 4
    for (int k = 0; k < INC; k++) {
        float w = sW[k * HIDC + j];
#pragma unroll
        for (int n = 0; n < 32; n++) acc[n] = fmaf(sF[n * INC + k], w, acc[n]);
    }
    float bj = b[j];
#pragma unroll
    for (int n = 0; n < 32; n++)
        h1[((long long)(n0 + n)) * HIDC + j] = fmaxf(acc[n] + bj, 0.0f);
}

// dual GEMM: s2 = h1 @ Wself2, p = h1 @ Wneigh2 (h1 tile read from gmem once)
__global__ __launch_bounds__(128) void k_dual(
    const float* __restrict__ h1,
    const float* __restrict__ Wself2, const float* __restrict__ Wneigh2,
    float* __restrict__ s2, float* __restrict__ p) {
    __shared__ float sW[HIDC * OUTC];  // 32 KB
    __shared__ float sF[32 * HIDC];    // 16 KB  (total = 48 KB)
    const int j = threadIdx.x & 63;
    const int g = threadIdx.x >> 6;
    const int n0 = blockIdx.x * 32;
    float accS[16], accP[16];
#pragma unroll
    for (int n = 0; n < 16; n++) { accS[n] = 0.0f; accP[n] = 0.0f; }

    {
        const float* hr = h1 + (long long)n0 * HIDC;
        for (int i = threadIdx.x; i < 32 * HIDC; i += 128) sF[i] = hr[i];
    }
    for (int i = threadIdx.x; i < HIDC * OUTC; i += 128) sW[i] = Wself2[i];
    __syncthreads();
#pragma unroll 4
    for (int k = 0; k < HIDC; k++) {
        float w = sW[k * OUTC + j];
#pragma unroll
        for (int n = 0; n < 16; n++)
            accS[n] = fmaf(sF[(g * 16 + n) * HIDC + k], w, accS[n]);
    }
    __syncthreads();
    for (int i = threadIdx.x; i < HIDC * OUTC; i += 128) sW[i] = Wneigh2[i];
    __syncthreads();
#pragma unroll 4
    for (int k = 0; k < HIDC; k++) {
        float w = sW[k * OUTC + j];
#pragma unroll
        for (int n = 0; n < 16; n++)
            accP[n] = fmaf(sF[(g * 16 + n) * HIDC + k], w, accP[n]);
    }
#pragma unroll
    for (int n = 0; n < 16; n++) {
        long long row = (long long)(n0 + g * 16 + n);
        s2[row * OUTC + j] = accS[n];
        p [row * OUTC + j] = accP[n];
    }
}

// elementwise: h2 = relu(s2 + aggp*dinv + b2), in place on s2 buffer
__global__ void k_ew(float* __restrict__ s2, const float* __restrict__ aggp,
                     const float* __restrict__ dinv, const float* __restrict__ b2) {
    long long idx = (long long)blockIdx.x * blockDim.x + threadIdx.x;
    if (idx >= (long long)NN * OUTC) return;
    int n = (int)(idx >> 6);
    int j = (int)(idx & 63);
    s2[idx] = fmaxf(s2[idx] + aggp[idx] * dinv[n] + b2[j], 0.0f);
}

// classifier: out = h2 @ wc + bc ; 12 nodes x 20 classes = 240 active threads/block
__global__ __launch_bounds__(256) void k_out(const float* __restrict__ h2,
                                             const float* __restrict__ wc,
                                             const float* __restrict__ bc,
                                             float* __restrict__ out) {
    __shared__ float sW[OUTC * NCLS];
    __shared__ float sB[NCLS];
    __shared__ float sH[12 * 65];   // pad to 65 to avoid stride-64 bank conflicts
    const int tid = threadIdx.x;
    const int n0 = blockIdx.x * 12;
    const int nmax = min(12, NN - n0);
    for (int i = tid; i < OUTC * NCLS; i += 256) sW[i] = wc[i];
    if (tid < NCLS) sB[tid] = bc[tid];
    for (int i = tid; i < nmax * OUTC; i += 256) {
        int ln = i >> 6, k = i & 63;
        sH[ln * 65 + k] = h2[(long long)(n0 + ln) * OUTC + k];
    }
    __syncthreads();
    if (tid < 240) {
        int ln = tid / 20, c = tid % 20;
        if (ln < nmax) {
            float acc = sB[c];
#pragma unroll
            for (int k = 0; k < OUTC; k++)
                acc = fmaf(sH[ln * 65 + k], sW[k * NCLS + c], acc);
            out[(long long)(n0 + ln) * NCLS + c] = acc;
        }
    }
}

// ---------------- launch ----------------------------------------------------
extern "C" void kernel_launch(void* const* d_in, const int* in_sizes, int n_in,
                              void* d_out, int out_size) {
    const float* x   = (const float*)d_in[0];
    const void*  ei  = d_in[1];
    const float* ws1 = (const float*)d_in[2];
    const float* wn1 = (const float*)d_in[3];
    const float* b1  = (const float*)d_in[4];
    const float* ws2 = (const float*)d_in[5];
    const float* wn2 = (const float*)d_in[6];
    const float* b2  = (const float*)d_in[7];
    const float* wc  = (const float*)d_in[8];
    const float* bc  = (const float*)d_in[9];
    float* out = (float*)d_out;

    const int nE = in_sizes[1] / 2;  // element count / 2, regardless of int width

    void *p_flag, *p_deg, *p_dinv, *p_agg1, *p_h1, *p_pp, *p_aggp, *p_h2;
    cudaGetSymbolAddress(&p_flag, g_is64);
    cudaGetSymbolAddress(&p_deg,  g_deg);
    cudaGetSymbolAddress(&p_dinv, g_dinv);
    cudaGetSymbolAddress(&p_agg1, g_agg1);
    cudaGetSymbolAddress(&p_h1,   g_h1);
    cudaGetSymbolAddress(&p_pp,   g_p);
    cudaGetSymbolAddress(&p_aggp, g_aggp);
    cudaGetSymbolAddress(&p_h2,   g_h2);
    int*   flag = (int*)p_flag;
    float* deg  = (float*)p_deg;
    float* dinv = (float*)p_dinv;
    float* agg1 = (float*)p_agg1;
    float* h1   = (float*)p_h1;
    float* pp   = (float*)p_pp;
    float* aggp = (float*)p_aggp;
    float* h2   = (float*)p_h2;

    // dtype detection (must precede edge kernels)
    k_detect<<<1, 256>>>((const int*)ei, in_sizes[1], flag);

    // zero scratch via kernel
    {
        long long na4 = (long long)NN * INC / 4;   // 1.6M
        long long nb4 = (long long)NN * OUTC / 4;  // 1.6M
        int blocks = (int)((na4 + 255) / 256);
        k_zero<<<blocks, 256>>>((float4*)agg1, na4, (float4*)aggp, nb4, deg, NN);
    }

    // degree + inverse
    k_deg<<<(nE + 255) / 256, 256>>>(ei, nE, deg, flag);
    k_deginv<<<(NN + 255) / 256, 256>>>(deg, dinv);

    // aggregate x (64-wide)
    {
        long long total = (long long)nE * 16;
        int blocks = (int)((total + 255) / 256);
        k_agg64<<<blocks, 256>>>((const float4*)x, ei, nE, agg1, flag);
    }

    // layer 1
    k_layer1<<<NN / 32, 128>>>(x, agg1, dinv, ws1, wn1, b1, h1);

    // dual projection: s2 (into h2 buffer) and p
    k_dual<<<NN / 32, 128>>>(h1, ws2, wn2, h2, pp);

    // aggregate p (64-wide)
    {
        long long total = (long long)nE * 16;
        int blocks = (int)((total + 255) / 256);
        k_agg64<<<blocks, 256>>>((const float4*)pp, ei, nE, aggp, flag);
    }

    // layer 2 epilogue (in place on h2)
    k_ew<<<(NN * OUTC + 255) / 256, 256>>>(h2, aggp, dinv, b2);

    // classifier
    k_out<<<(NN + 11) / 12, 256>>>(h2, wc, bc, out);
}

// round 5
// speedup vs baseline: 1.3994x; 1.3994x over previous
#include <cuda_runtime.h>
#include <cuda_bf16.h>

#define NN 100000
#define NE_MAX 1600000
#define INC 64
#define HIDC 128
#define OUTC 64
#define NCLS 20

// ---------------- device scratch (static globals; no allocation) ------------
__device__ int   g_is64;
__device__ __align__(16) int2  g_edges[NE_MAX];  // packed (src,dst), clamped
__device__ float g_deg[NN];
__device__ float g_dinv[NN];
__device__ __align__(16) float g_agg1[(size_t)NN * INC];
__device__ __align__(16) float g_h1[(size_t)NN * HIDC];
__device__ __align__(16) float g_p[(size_t)NN * OUTC];
__device__ __align__(16) float g_aggp[(size_t)NN * OUTC];
__device__ __align__(16) float g_h2[(size_t)NN * OUTC];  // s2 then h2 in-place

// ---------------- kernels ---------------------------------------------------

// Detect edge dtype: if data is int64 (values < 2^31), every odd int32 word is 0.
__global__ void k_detect(const int* __restrict__ ei32, int n32, int* __restrict__ flag) {
    __shared__ int s_any;
    if (threadIdx.x == 0) s_any = 0;
    __syncthreads();
    int nonzero = 0;
    int limit = n32 < 16384 ? n32 : 16384;
    for (int i = 1 + 2 * threadIdx.x; i < limit; i += 2 * blockDim.x)
        if (ei32[i] != 0) nonzero = 1;
    if (nonzero) atomicOr(&s_any, 1);
    __syncthreads();
    if (threadIdx.x == 0) *flag = (s_any == 0) ? 1 : 0;  // all-zero odd words -> int64
}

// zero-fill scratch
__global__ void k_zero(float4* __restrict__ a, long long na4,
                       float4* __restrict__ b, long long nb4,
                       float* __restrict__ c, int nc) {
    long long i = (long long)blockIdx.x * blockDim.x + threadIdx.x;
    const float4 z = make_float4(0.f, 0.f, 0.f, 0.f);
    if (i < na4) a[i] = z;
    if (i < nb4) b[i] = z;
    if (i < nc) c[i] = 0.f;
}

// Convert edge index to packed int2 (clamped) + accumulate degree.
__global__ void k_convert(const void* __restrict__ ei, int nE, int2* __restrict__ edges,
                          float* __restrict__ deg, const int* __restrict__ flag) {
    int e = blockIdx.x * blockDim.x + threadIdx.x;
    if (e >= nE) return;
    int s, d;
    if (*flag) {
        s = (int)((const long long*)ei)[e];
        d = (int)((const long long*)ei)[(long long)nE + e];
    } else {
        s = ((const int*)ei)[e];
        d = ((const int*)ei)[nE + e];
    }
    if ((unsigned)s >= NN) s = 0;
    if ((unsigned)d >= NN) d = 0;
    edges[e] = make_int2(s, d);
    atomicAdd(&deg[d], 1.0f);
}

__global__ void k_deginv(const float* __restrict__ deg, float* __restrict__ dinv) {
    int i = blockIdx.x * blockDim.x + threadIdx.x;
    if (i < NN) dinv[i] = 1.0f / fmaxf(deg[i], 1.0f);
}

// segment-sum of a 64-wide feature table along edges: 16 threads/edge.
// float4 gather + one red.global.add.v4.f32 (single L2 reduction op per 16B).
__global__ void k_agg64(const float4* __restrict__ feat, const int2* __restrict__ edges,
                        int nE, float4* __restrict__ agg) {
    long long idx = (long long)blockIdx.x * blockDim.x + threadIdx.x;
    long long total = (long long)nE * 16;
    if (idx >= total) return;
    int e = (int)(idx >> 4);
    int c = (int)(idx & 15);
    int2 ed = __ldg(&edges[e]);
    float4 v = __ldg(&feat[(long long)ed.x * 16 + c]);
    float4* a = agg + (long long)ed.y * 16 + c;
    asm volatile("red.global.add.v4.f32 [%0], {%1,%2,%3,%4};"
                 :: "l"(a), "f"(v.x), "f"(v.y), "f"(v.z), "f"(v.w) : "memory");
}

// layer1: h1[n][j] = relu( sum_k x[n][k]*Ws[k][j] + (agg1[n][k]*dinv[n])*Wn[k][j] + b[j] )
__global__ __launch_bounds__(128) void k_layer1(
    const float* __restrict__ x, const float* __restrict__ agg,
    const float* __restrict__ dinv,
    const float* __restrict__ Wself, const float* __restrict__ Wneigh,
    const float* __restrict__ b, float* __restrict__ h1) {
    __shared__ float sW[INC * HIDC];   // 32 KB
    __shared__ float sF[32 * INC];     // 8 KB
    __shared__ float sD[32];
    const int j = threadIdx.x;
    const int n0 = blockIdx.x * 32;
    float acc[32];
#pragma unroll
    for (int n = 0; n < 32; n++) acc[n] = 0.0f;

    if (j < 32) sD[j] = dinv[n0 + j];
    for (int i = j; i < INC * HIDC; i += 128) sW[i] = Wself[i];
    {
        const float* xr = x + (long long)n0 * INC;
        for (int i = j; i < 32 * INC; i += 128) sF[i] = xr[i];
    }
    __syncthreads();
#pragma unroll 4
    for (int k = 0; k < INC; k++) {
        float w = sW[k * HIDC + j];
#pragma unroll
        for (int n = 0; n < 32; n++) acc[n] = fmaf(sF[n * INC + k], w, acc[n]);
    }
    __syncthreads();
    for (int i = j; i < INC * HIDC; i += 128) sW[i] = Wneigh[i];
    {
        const float* ar = agg + (long long)n0 * INC;
        for (int i = j; i < 32 * INC; i += 128) sF[i] = ar[i] * sD[i >> 6];
    }
    __syncthreads();
#pragma unroll 4
    for (int k = 0; k < INC; k++) {
        float w = sW[k * HIDC + j];
#pragma unroll
        for (int n = 0; n < 32; n++) acc[n] = fmaf(sF[n * INC + k], w, acc[n]);
    }
    float bj = b[j];
#pragma unroll
    for (int n = 0; n < 32; n++)
        h1[((long long)(n0 + n)) * HIDC + j] = fmaxf(acc[n] + bj, 0.0f);
}

// dual GEMM: s2 = h1 @ Wself2, p = h1 @ Wneigh2 (h1 tile read from gmem once)
__global__ __launch_bounds__(128) void k_dual(
    const float* __restrict__ h1,
    const float* __restrict__ Wself2, const float* __restrict__ Wneigh2,
    float* __restrict__ s2, float* __restrict__ p) {
    __shared__ float sW[HIDC * OUTC];  // 32 KB
    __shared__ float sF[32 * HIDC];    // 16 KB  (total = 48 KB)
    const int j = threadIdx.x & 63;
    const int g = threadIdx.x >> 6;
    const int n0 = blockIdx.x * 32;
    float accS[16], accP[16];
#pragma unroll
    for (int n = 0; n < 16; n++) { accS[n] = 0.0f; accP[n] = 0.0f; }

    {
        const float* hr = h1 + (long long)n0 * HIDC;
        for (int i = threadIdx.x; i < 32 * HIDC; i += 128) sF[i] = hr[i];
    }
    for (int i = threadIdx.x; i < HIDC * OUTC; i += 128) sW[i] = Wself2[i];
    __syncthreads();
#pragma unroll 4
    for (int k = 0; k < HIDC; k++) {
        float w = sW[k * OUTC + j];
#pragma unroll
        for (int n = 0; n < 16; n++)
            accS[n] = fmaf(sF[(g * 16 + n) * HIDC + k], w, accS[n]);
    }
    __syncthreads();
    for (int i = threadIdx.x; i < HIDC * OUTC; i += 128) sW[i] = Wneigh2[i];
    __syncthreads();
#pragma unroll 4
    for (int k = 0; k < HIDC; k++) {
        float w = sW[k * OUTC + j];
#pragma unroll
        for (int n = 0; n < 16; n++)
            accP[n] = fmaf(sF[(g * 16 + n) * HIDC + k], w, accP[n]);
    }
#pragma unroll
    for (int n = 0; n < 16; n++) {
        long long row = (long long)(n0 + g * 16 + n);
        s2[row * OUTC + j] = accS[n];
        p [row * OUTC + j] = accP[n];
    }
}

// elementwise: h2 = relu(s2 + aggp*dinv + b2), in place on s2 buffer
__global__ void k_ew(float* __restrict__ s2, const float* __restrict__ aggp,
                     const float* __restrict__ dinv, const float* __restrict__ b2) {
    long long idx = (long long)blockIdx.x * blockDim.x + threadIdx.x;
    if (idx >= (long long)NN * OUTC) return;
    int n = (int)(idx >> 6);
    int j = (int)(idx & 63);
    s2[idx] = fmaxf(s2[idx] + aggp[idx] * dinv[n] + b2[j], 0.0f);
}

// classifier: out = h2 @ wc + bc ; 12 nodes x 20 classes = 240 active threads/block
__global__ __launch_bounds__(256) void k_out(const float* __restrict__ h2,
                                             const float* __restrict__ wc,
                                             const float* __restrict__ bc,
                                             float* __restrict__ out) {
    __shared__ float sW[OUTC * NCLS];
    __shared__ float sB[NCLS];
    __shared__ float sH[12 * 65];   // pad to 65 to avoid stride-64 bank conflicts
    const int tid = threadIdx.x;
    const int n0 = blockIdx.x * 12;
    const int nmax = min(12, NN - n0);
    for (int i = tid; i < OUTC * NCLS; i += 256) sW[i] = wc[i];
    if (tid < NCLS) sB[tid] = bc[tid];
    for (int i = tid; i < nmax * OUTC; i += 256) {
        int ln = i >> 6, k = i & 63;
        sH[ln * 65 + k] = h2[(long long)(n0 + ln) * OUTC + k];
    }
    __syncthreads();
    if (tid < 240) {
        int ln = tid / 20, c = tid % 20;
        if (ln < nmax) {
            float acc = sB[c];
#pragma unroll
            for (int k = 0; k < OUTC; k++)
                acc = fmaf(sH[ln * 65 + k], sW[k * NCLS + c], acc);
            out[(long long)(n0 + ln) * NCLS + c] = acc;
        }
    }
}

// ---------------- launch ----------------------------------------------------
extern "C" void kernel_launch(void* const* d_in, const int* in_sizes, int n_in,
                              void* d_out, int out_size) {
    const float* x   = (const float*)d_in[0];
    const void*  ei  = d_in[1];
    const float* ws1 = (const float*)d_in[2];
    const float* wn1 = (const float*)d_in[3];
    const float* b1  = (const float*)d_in[4];
    const float* ws2 = (const float*)d_in[5];
    const float* wn2 = (const float*)d_in[6];
    const float* b2  = (const float*)d_in[7];
    const float* wc  = (const float*)d_in[8];
    const float* bc  = (const float*)d_in[9];
    float* out = (float*)d_out;

    int nE = in_sizes[1] / 2;
    if (nE > NE_MAX) nE = NE_MAX;

    void *p_flag, *p_edges, *p_deg, *p_dinv, *p_agg1, *p_h1, *p_pp, *p_aggp, *p_h2;
    cudaGetSymbolAddress(&p_flag, g_is64);
    cudaGetSymbolAddress(&p_edges, g_edges);
    cudaGetSymbolAddress(&p_deg,  g_deg);
    cudaGetSymbolAddress(&p_dinv, g_dinv);
    cudaGetSymbolAddress(&p_agg1, g_agg1);
    cudaGetSymbolAddress(&p_h1,   g_h1);
    cudaGetSymbolAddress(&p_pp,   g_p);
    cudaGetSymbolAddress(&p_aggp, g_aggp);
    cudaGetSymbolAddress(&p_h2,   g_h2);
    int*   flag  = (int*)p_flag;
    int2*  edges = (int2*)p_edges;
    float* deg   = (float*)p_deg;
    float* dinv  = (float*)p_dinv;
    float* agg1  = (float*)p_agg1;
    float* h1    = (float*)p_h1;
    float* pp    = (float*)p_pp;
    float* aggp  = (float*)p_aggp;
    float* h2    = (float*)p_h2;

    // dtype detection (must precede edge kernels)
    k_detect<<<1, 256>>>((const int*)ei, in_sizes[1], flag);

    // zero scratch
    {
        long long na4 = (long long)NN * INC / 4;
        long long nb4 = (long long)NN * OUTC / 4;
        int blocks = (int)((na4 + 255) / 256);
        k_zero<<<blocks, 256>>>((float4*)agg1, na4, (float4*)aggp, nb4, deg, NN);
    }

    // edge convert + degree, then inverse
    k_convert<<<(nE + 255) / 256, 256>>>(ei, nE, edges, deg, flag);
    k_deginv<<<(NN + 255) / 256, 256>>>(deg, dinv);

    // aggregate x (64-wide)
    {
        long long total = (long long)nE * 16;
        int blocks = (int)((total + 255) / 256);
        k_agg64<<<blocks, 256>>>((const float4*)x, edges, nE, (float4*)agg1);
    }

    // layer 1
    k_layer1<<<NN / 32, 128>>>(x, agg1, dinv, ws1, wn1, b1, h1);

    // dual projection: s2 (into h2 buffer) and p
    k_dual<<<NN / 32, 128>>>(h1, ws2, wn2, h2, pp);

    // aggregate p (64-wide)
    {
        long long total = (long long)nE * 16;
        int blocks = (int)((total + 255) / 256);
        k_agg64<<<blocks, 256>>>((const float4*)pp, edges, nE, (float4*)aggp);
    }

    // layer 2 epilogue (in place on h2)
    k_ew<<<(NN * OUTC + 255) / 256, 256>>>(h2, aggp, dinv, b2);

    // classifier
    k_out<<<(NN + 11) / 12, 256>>>(h2, wc, bc, out);
}

// round 6
// speedup vs baseline: 1.6774x; 1.1987x over previous
#include <cuda_runtime.h>
#include <cuda_bf16.h>

#define NN 100000
#define NE_MAX 1600000
#define INC 64
#define HIDC 128
#define OUTC 64
#define NCLS 20
#define NCHUNK 98          // ceil(NN/1024)

// ---------------- device scratch (static globals; no allocation) ------------
__device__ int   g_is64;
__device__ __align__(16) int2 g_edges[NE_MAX];
__device__ int   g_degi[NN];
__device__ int   g_rowstart[NN];
__device__ int   g_cursor[NN];
__device__ int   g_srclist[NE_MAX];
__device__ int   g_chunksum[NCHUNK];
__device__ int   g_chunkoff[NCHUNK];
__device__ float g_dinv[NN];
__device__ __align__(16) float g_agg1[(size_t)NN * INC];   // normalized h_neigh1
__device__ __align__(16) float g_h1[(size_t)NN * HIDC];
__device__ __align__(16) float g_p[(size_t)NN * OUTC];
__device__ __align__(16) float g_s2[(size_t)NN * OUTC];
__device__ __align__(16) float g_h2[(size_t)NN * OUTC];

// ---------------- kernels ---------------------------------------------------

// Detect edge dtype: int64 (values < 2^31) -> every odd int32 word is 0.
__global__ void k_detect(const int* __restrict__ ei32, int n32, int* __restrict__ flag) {
    __shared__ int s_any;
    if (threadIdx.x == 0) s_any = 0;
    __syncthreads();
    int nonzero = 0;
    int limit = n32 < 16384 ? n32 : 16384;
    for (int i = 1 + 2 * threadIdx.x; i < limit; i += 2 * blockDim.x)
        if (ei32[i] != 0) nonzero = 1;
    if (nonzero) atomicOr(&s_any, 1);
    __syncthreads();
    if (threadIdx.x == 0) *flag = (s_any == 0) ? 1 : 0;
}

__global__ void k_zero_deg(int* __restrict__ degi) {
    int i = blockIdx.x * blockDim.x + threadIdx.x;
    if (i < NN) degi[i] = 0;
}

// Convert edge index (int32/int64) to packed int2 (clamped) + int degree count.
__global__ void k_convert(const void* __restrict__ ei, int nE, int2* __restrict__ edges,
                          int* __restrict__ degi, const int* __restrict__ flag) {
    int e = blockIdx.x * blockDim.x + threadIdx.x;
    if (e >= nE) return;
    int s, d;
    if (*flag) {
        s = (int)((const long long*)ei)[e];
        d = (int)((const long long*)ei)[(long long)nE + e];
    } else {
        s = ((const int*)ei)[e];
        d = ((const int*)ei)[nE + e];
    }
    if ((unsigned)s >= NN) s = 0;
    if ((unsigned)d >= NN) d = 0;
    edges[e] = make_int2(s, d);
    atomicAdd(&degi[d], 1);
}

// scan A: per-1024 chunk sums of degi
__global__ __launch_bounds__(1024) void k_scanA(const int* __restrict__ degi,
                                                int* __restrict__ chunksum) {
    __shared__ int s[1024];
    int i = blockIdx.x * 1024 + threadIdx.x;
    s[threadIdx.x] = (i < NN) ? degi[i] : 0;
    __syncthreads();
    for (int off = 512; off > 0; off >>= 1) {
        if (threadIdx.x < off) s[threadIdx.x] += s[threadIdx.x + off];
        __syncthreads();
    }
    if (threadIdx.x == 0) chunksum[blockIdx.x] = s[0];
}

// scan B: exclusive scan of NCHUNK chunk sums (single block)
__global__ void k_scanB(const int* __restrict__ chunksum, int* __restrict__ chunkoff) {
    __shared__ int s[128];
    int v = (threadIdx.x < NCHUNK) ? chunksum[threadIdx.x] : 0;
    s[threadIdx.x] = v;
    __syncthreads();
    for (int off = 1; off < 128; off <<= 1) {
        int t = (threadIdx.x >= off) ? s[threadIdx.x - off] : 0;
        __syncthreads();
        s[threadIdx.x] += t;
        __syncthreads();
    }
    if (threadIdx.x < NCHUNK) chunkoff[threadIdx.x] = s[threadIdx.x] - v;
}

// scan C: exclusive scan within chunk + chunk offset -> rowstart, cursor
__global__ __launch_bounds__(1024) void k_scanC(const int* __restrict__ degi,
                                                const int* __restrict__ chunkoff,
                                                int* __restrict__ rowstart,
                                                int* __restrict__ cursor) {
    __shared__ int s[1024];
    int i = blockIdx.x * 1024 + threadIdx.x;
    int v = (i < NN) ? degi[i] : 0;
    s[threadIdx.x] = v;
    __syncthreads();
    for (int off = 1; off < 1024; off <<= 1) {
        int t = (threadIdx.x >= off) ? s[threadIdx.x - off] : 0;
        __syncthreads();
        s[threadIdx.x] += t;
        __syncthreads();
    }
    if (i < NN) {
        int excl = s[threadIdx.x] - v + chunkoff[blockIdx.x];
        rowstart[i] = excl;
        cursor[i] = excl;
    }
}

__global__ void k_deginv(const int* __restrict__ degi, float* __restrict__ dinv) {
    int i = blockIdx.x * blockDim.x + threadIdx.x;
    if (i < NN) dinv[i] = 1.0f / fmaxf((float)degi[i], 1.0f);
}

// scatter edges into per-dst src lists
__global__ void k_scatter(const int2* __restrict__ edges, int nE,
                          int* __restrict__ cursor, int* __restrict__ srclist) {
    int e = blockIdx.x * blockDim.x + threadIdx.x;
    if (e >= nE) return;
    int2 ed = edges[e];
    int p = atomicAdd(&cursor[ed.y], 1);
    srclist[p] = ed.x;
}

// gather-aggregate 64-wide: one warp per node, 2 edges per iteration.
// out[node] = (sum of feat[src]) * dinv[node]
__global__ __launch_bounds__(256) void k_gather1(
    const float4* __restrict__ feat, const int* __restrict__ rowstart,
    const int* __restrict__ degi, const int* __restrict__ srclist,
    const float* __restrict__ dinv, float4* __restrict__ out) {
    int node = blockIdx.x * 8 + (threadIdx.x >> 5);
    if (node >= NN) return;
    int lane = threadIdx.x & 31;
    int half = lane >> 4;
    int c = lane & 15;
    int beg = rowstart[node];
    int cnt = degi[node];
    float4 acc = make_float4(0.f, 0.f, 0.f, 0.f);
    for (int i = half; i < cnt; i += 2) {
        int s = __ldg(&srclist[beg + i]);
        float4 v = __ldg(&feat[(long long)s * 16 + c]);
        acc.x += v.x; acc.y += v.y; acc.z += v.z; acc.w += v.w;
    }
    acc.x += __shfl_xor_sync(0xffffffffu, acc.x, 16);
    acc.y += __shfl_xor_sync(0xffffffffu, acc.y, 16);
    acc.z += __shfl_xor_sync(0xffffffffu, acc.z, 16);
    acc.w += __shfl_xor_sync(0xffffffffu, acc.w, 16);
    if (half == 0) {
        float di = dinv[node];
        out[(long long)node * 16 + c] =
            make_float4(acc.x * di, acc.y * di, acc.z * di, acc.w * di);
    }
}

// gather-aggregate + layer2 epilogue: h2 = relu(s2 + agg(p)*dinv + b2)
__global__ __launch_bounds__(256) void k_gather2(
    const float4* __restrict__ pfeat, const int* __restrict__ rowstart,
    const int* __restrict__ degi, const int* __restrict__ srclist,
    const float* __restrict__ dinv, const float4* __restrict__ s2,
    const float4* __restrict__ b2, float4* __restrict__ h2) {
    int node = blockIdx.x * 8 + (threadIdx.x >> 5);
    if (node >= NN) return;
    int lane = threadIdx.x & 31;
    int half = lane >> 4;
    int c = lane & 15;
    int beg = rowstart[node];
    int cnt = degi[node];
    float4 acc = make_float4(0.f, 0.f, 0.f, 0.f);
    for (int i = half; i < cnt; i += 2) {
        int s = __ldg(&srclist[beg + i]);
        float4 v = __ldg(&pfeat[(long long)s * 16 + c]);
        acc.x += v.x; acc.y += v.y; acc.z += v.z; acc.w += v.w;
    }
    acc.x += __shfl_xor_sync(0xffffffffu, acc.x, 16);
    acc.y += __shfl_xor_sync(0xffffffffu, acc.y, 16);
    acc.z += __shfl_xor_sync(0xffffffffu, acc.z, 16);
    acc.w += __shfl_xor_sync(0xffffffffu, acc.w, 16);
    if (half == 0) {
        float di = dinv[node];
        float4 sv = __ldg(&s2[(long long)node * 16 + c]);
        float4 bv = __ldg(&b2[c]);
        float4 r;
        r.x = fmaxf(sv.x + acc.x * di + bv.x, 0.f);
        r.y = fmaxf(sv.y + acc.y * di + bv.y, 0.f);
        r.z = fmaxf(sv.z + acc.z * di + bv.z, 0.f);
        r.w = fmaxf(sv.w + acc.w * di + bv.w, 0.f);
        h2[(long long)node * 16 + c] = r;
    }
}

// layer1: h1[n][j] = relu( sum_k x[n][k]*Ws[k][j] + agg1[n][k]*Wn[k][j] + b[j] )
// (agg1 pre-normalized by dinv)
__global__ __launch_bounds__(128) void k_layer1(
    const float* __restrict__ x, const float* __restrict__ agg,
    const float* __restrict__ Wself, const float* __restrict__ Wneigh,
    const float* __restrict__ b, float* __restrict__ h1) {
    __shared__ float sW[INC * HIDC];   // 32 KB
    __shared__ float sF[32 * INC];     // 8 KB
    const int j = threadIdx.x;
    const int n0 = blockIdx.x * 32;
    float acc[32];
#pragma unroll
    for (int n = 0; n < 32; n++) acc[n] = 0.0f;

    for (int i = j; i < INC * HIDC; i += 128) sW[i] = Wself[i];
    {
        const float* xr = x + (long long)n0 * INC;
        for (int i = j; i < 32 * INC; i += 128) sF[i] = xr[i];
    }
    __syncthreads();
#pragma unroll 4
    for (int k = 0; k < INC; k++) {
        float w = sW[k * HIDC + j];
#pragma unroll
        for (int n = 0; n < 32; n++) acc[n] = fmaf(sF[n * INC + k], w, acc[n]);
    }
    __syncthreads();
    for (int i = j; i < INC * HIDC; i += 128) sW[i] = Wneigh[i];
    {
        const float* ar = agg + (long long)n0 * INC;
        for (int i = j; i < 32 * INC; i += 128) sF[i] = ar[i];
    }
    __syncthreads();
#pragma unroll 4
    for (int k = 0; k < INC; k++) {
        float w = sW[k * HIDC + j];
#pragma unroll
        for (int n = 0; n < 32; n++) acc[n] = fmaf(sF[n * INC + k], w, acc[n]);
    }
    float bj = b[j];
#pragma unroll
    for (int n = 0; n < 32; n++)
        h1[((long long)(n0 + n)) * HIDC + j] = fmaxf(acc[n] + bj, 0.0f);
}

// dual GEMM: s2 = h1 @ Wself2, p = h1 @ Wneigh2
__global__ __launch_bounds__(128) void k_dual(
    const float* __restrict__ h1,
    const float* __restrict__ Wself2, const float* __restrict__ Wneigh2,
    float* __restrict__ s2, float* __restrict__ p) {
    __shared__ float sW[HIDC * OUTC];  // 32 KB
    __shared__ float sF[32 * HIDC];    // 16 KB
    const int j = threadIdx.x & 63;
    const int g = threadIdx.x >> 6;
    const int n0 = blockIdx.x * 32;
    float accS[16], accP[16];
#pragma unroll
    for (int n = 0; n < 16; n++) { accS[n] = 0.0f; accP[n] = 0.0f; }

    {
        const float* hr = h1 + (long long)n0 * HIDC;
        for (int i = threadIdx.x; i < 32 * HIDC; i += 128) sF[i] = hr[i];
    }
    for (int i = threadIdx.x; i < HIDC * OUTC; i += 128) sW[i] = Wself2[i];
    __syncthreads();
#pragma unroll 4
    for (int k = 0; k < HIDC; k++) {
        float w = sW[k * OUTC + j];
#pragma unroll
        for (int n = 0; n < 16; n++)
            accS[n] = fmaf(sF[(g * 16 + n) * HIDC + k], w, accS[n]);
    }
    __syncthreads();
    for (int i = threadIdx.x; i < HIDC * OUTC; i += 128) sW[i] = Wneigh2[i];
    __syncthreads();
#pragma unroll 4
    for (int k = 0; k < HIDC; k++) {
        float w = sW[k * OUTC + j];
#pragma unroll
        for (int n = 0; n < 16; n++)
            accP[n] = fmaf(sF[(g * 16 + n) * HIDC + k], w, accP[n]);
    }
#pragma unroll
    for (int n = 0; n < 16; n++) {
        long long row = (long long)(n0 + g * 16 + n);
        s2[row * OUTC + j] = accS[n];
        p [row * OUTC + j] = accP[n];
    }
}

// classifier: out = h2 @ wc + bc
__global__ __launch_bounds__(256) void k_out(const float* __restrict__ h2,
                                             const float* __restrict__ wc,
                                             const float* __restrict__ bc,
                                             float* __restrict__ out) {
    __shared__ float sW[OUTC * NCLS];
    __shared__ float sB[NCLS];
    __shared__ float sH[12 * 65];
    const int tid = threadIdx.x;
    const int n0 = blockIdx.x * 12;
    const int nmax = min(12, NN - n0);
    for (int i = tid; i < OUTC * NCLS; i += 256) sW[i] = wc[i];
    if (tid < NCLS) sB[tid] = bc[tid];
    for (int i = tid; i < nmax * OUTC; i += 256) {
        int ln = i >> 6, k = i & 63;
        sH[ln * 65 + k] = h2[(long long)(n0 + ln) * OUTC + k];
    }
    __syncthreads();
    if (tid < 240) {
        int ln = tid / 20, c = tid % 20;
        if (ln < nmax) {
            float acc = sB[c];
#pragma unroll
            for (int k = 0; k < OUTC; k++)
                acc = fmaf(sH[ln * 65 + k], sW[k * NCLS + c], acc);
            out[(long long)(n0 + ln) * NCLS + c] = acc;
        }
    }
}

// ---------------- launch ----------------------------------------------------
extern "C" void kernel_launch(void* const* d_in, const int* in_sizes, int n_in,
                              void* d_out, int out_size) {
    const float* x   = (const float*)d_in[0];
    const void*  ei  = d_in[1];
    const float* ws1 = (const float*)d_in[2];
    const float* wn1 = (const float*)d_in[3];
    const float* b1  = (const float*)d_in[4];
    const float* ws2 = (const float*)d_in[5];
    const float* wn2 = (const float*)d_in[6];
    const float* b2  = (const float*)d_in[7];
    const float* wc  = (const float*)d_in[8];
    const float* bc  = (const float*)d_in[9];
    float* out = (float*)d_out;

    int nE = in_sizes[1] / 2;
    if (nE > NE_MAX) nE = NE_MAX;

    void *p_flag, *p_edges, *p_degi, *p_rs, *p_cur, *p_src, *p_cs, *p_co;
    void *p_dinv, *p_agg1, *p_h1, *p_pp, *p_s2, *p_h2;
    cudaGetSymbolAddress(&p_flag, g_is64);
    cudaGetSymbolAddress(&p_edges, g_edges);
    cudaGetSymbolAddress(&p_degi, g_degi);
    cudaGetSymbolAddress(&p_rs,   g_rowstart);
    cudaGetSymbolAddress(&p_cur,  g_cursor);
    cudaGetSymbolAddress(&p_src,  g_srclist);
    cudaGetSymbolAddress(&p_cs,   g_chunksum);
    cudaGetSymbolAddress(&p_co,   g_chunkoff);
    cudaGetSymbolAddress(&p_dinv, g_dinv);
    cudaGetSymbolAddress(&p_agg1, g_agg1);
    cudaGetSymbolAddress(&p_h1,   g_h1);
    cudaGetSymbolAddress(&p_pp,   g_p);
    cudaGetSymbolAddress(&p_s2,   g_s2);
    cudaGetSymbolAddress(&p_h2,   g_h2);
    int*   flag  = (int*)p_flag;
    int2*  edges = (int2*)p_edges;
    int*   degi  = (int*)p_degi;
    int*   rs    = (int*)p_rs;
    int*   cur   = (int*)p_cur;
    int*   src   = (int*)p_src;
    int*   cs    = (int*)p_cs;
    int*   co    = (int*)p_co;
    float* dinv  = (float*)p_dinv;
    float* agg1  = (float*)p_agg1;
    float* h1    = (float*)p_h1;
    float* pp    = (float*)p_pp;
    float* s2    = (float*)p_s2;
    float* h2    = (float*)p_h2;

    // dtype detect + CSR build
    k_detect<<<1, 256>>>((const int*)ei, in_sizes[1], flag);
    k_zero_deg<<<(NN + 255) / 256, 256>>>(degi);
    k_convert<<<(nE + 255) / 256, 256>>>(ei, nE, edges, degi, flag);
    k_scanA<<<NCHUNK, 1024>>>(degi, cs);
    k_scanB<<<1, 128>>>(cs, co);
    k_scanC<<<NCHUNK, 1024>>>(degi, co, rs, cur);
    k_deginv<<<(NN + 255) / 256, 256>>>(degi, dinv);
    k_scatter<<<(nE + 255) / 256, 256>>>(edges, nE, cur, src);

    // layer 1: gather-agg (normalized), then GEMM
    k_gather1<<<(NN + 7) / 8, 256>>>((const float4*)x, rs, degi, src, dinv,
                                     (float4*)agg1);
    k_layer1<<<NN / 32, 128>>>(x, agg1, ws1, wn1, b1, h1);

    // layer 2: dual projection, gather-agg fused with epilogue
    k_dual<<<NN / 32, 128>>>(h1, ws2, wn2, s2, pp);
    k_gather2<<<(NN + 7) / 8, 256>>>((const float4*)pp, rs, degi, src, dinv,
                                     (const float4*)s2, (const float4*)b2,
                                     (float4*)h2);

    // classifier
    k_out<<<(NN + 11) / 12, 256>>>(h2, wc, bc, out);
}

// round 7
// speedup vs baseline: 2.5845x; 1.5407x over previous
#include <cuda_runtime.h>
#include <cuda_bf16.h>

#define NN 100000
#define NE_MAX 1600000
#define INC 64
#define HIDC 128
#define OUTC 64
#define NCLS 20
#define NCHUNK 98          // ceil(NN/1024)

// ---------------- device scratch (static globals; no allocation) ------------
__device__ int   g_is64;
__device__ __align__(16) int2 g_edges[NE_MAX];
__device__ int   g_degi[NN];
__device__ int   g_rowstart[NN];
__device__ int   g_cursor[NN];
__device__ int   g_srclist[NE_MAX];
__device__ int   g_chunksum[NCHUNK];
__device__ int   g_chunkoff[NCHUNK];
__device__ float g_dinv[NN];
__device__ __align__(16) float g_agg1[(size_t)NN * INC];   // normalized h_neigh1
__device__ __align__(16) float g_h1[(size_t)NN * HIDC];
__device__ __align__(16) float g_p[(size_t)NN * OUTC];
__device__ __align__(16) float g_s2[(size_t)NN * OUTC];
__device__ __align__(16) float g_h2[(size_t)NN * OUTC];

// ---------------- CSR build kernels -----------------------------------------

__global__ void k_detect(const int* __restrict__ ei32, int n32, int* __restrict__ flag) {
    __shared__ int s_any;
    if (threadIdx.x == 0) s_any = 0;
    __syncthreads();
    int nonzero = 0;
    int limit = n32 < 16384 ? n32 : 16384;
    for (int i = 1 + 2 * threadIdx.x; i < limit; i += 2 * blockDim.x)
        if (ei32[i] != 0) nonzero = 1;
    if (nonzero) atomicOr(&s_any, 1);
    __syncthreads();
    if (threadIdx.x == 0) *flag = (s_any == 0) ? 1 : 0;  // all-zero odd words -> int64
}

__global__ void k_zero_deg(int* __restrict__ degi) {
    int i = blockIdx.x * blockDim.x + threadIdx.x;
    if (i < NN) degi[i] = 0;
}

__global__ void k_convert(const void* __restrict__ ei, int nE, int2* __restrict__ edges,
                          int* __restrict__ degi, const int* __restrict__ flag) {
    int e = blockIdx.x * blockDim.x + threadIdx.x;
    if (e >= nE) return;
    int s, d;
    if (*flag) {
        s = (int)((const long long*)ei)[e];
        d = (int)((const long long*)ei)[(long long)nE + e];
    } else {
        s = ((const int*)ei)[e];
        d = ((const int*)ei)[nE + e];
    }
    if ((unsigned)s >= NN) s = 0;
    if ((unsigned)d >= NN) d = 0;
    edges[e] = make_int2(s, d);
    atomicAdd(&degi[d], 1);
}

__global__ __launch_bounds__(1024) void k_scanA(const int* __restrict__ degi,
                                                int* __restrict__ chunksum) {
    __shared__ int s[1024];
    int i = blockIdx.x * 1024 + threadIdx.x;
    s[threadIdx.x] = (i < NN) ? degi[i] : 0;
    __syncthreads();
    for (int off = 512; off > 0; off >>= 1) {
        if (threadIdx.x < off) s[threadIdx.x] += s[threadIdx.x + off];
        __syncthreads();
    }
    if (threadIdx.x == 0) chunksum[blockIdx.x] = s[0];
}

__global__ void k_scanB(const int* __restrict__ chunksum, int* __restrict__ chunkoff) {
    __shared__ int s[128];
    int v = (threadIdx.x < NCHUNK) ? chunksum[threadIdx.x] : 0;
    s[threadIdx.x] = v;
    __syncthreads();
    for (int off = 1; off < 128; off <<= 1) {
        int t = (threadIdx.x >= off) ? s[threadIdx.x - off] : 0;
        __syncthreads();
        s[threadIdx.x] += t;
        __syncthreads();
    }
    if (threadIdx.x < NCHUNK) chunkoff[threadIdx.x] = s[threadIdx.x] - v;
}

// scan C: exclusive scan within chunk + chunk offset -> rowstart, cursor, dinv
__global__ __launch_bounds__(1024) void k_scanC(const int* __restrict__ degi,
                                                const int* __restrict__ chunkoff,
                                                int* __restrict__ rowstart,
                                                int* __restrict__ cursor,
                                                float* __restrict__ dinv) {
    __shared__ int s[1024];
    int i = blockIdx.x * 1024 + threadIdx.x;
    int v = (i < NN) ? degi[i] : 0;
    s[threadIdx.x] = v;
    __syncthreads();
    for (int off = 1; off < 1024; off <<= 1) {
        int t = (threadIdx.x >= off) ? s[threadIdx.x - off] : 0;
        __syncthreads();
        s[threadIdx.x] += t;
        __syncthreads();
    }
    if (i < NN) {
        int excl = s[threadIdx.x] - v + chunkoff[blockIdx.x];
        rowstart[i] = excl;
        cursor[i] = excl;
        dinv[i] = 1.0f / fmaxf((float)v, 1.0f);
    }
}

__global__ void k_scatter(const int2* __restrict__ edges, int nE,
                          int* __restrict__ cursor, int* __restrict__ srclist) {
    int e = blockIdx.x * blockDim.x + threadIdx.x;
    if (e >= nE) return;
    int2 ed = edges[e];
    int p = atomicAdd(&cursor[ed.y], 1);
    srclist[p] = ed.x;
}

// ---------------- gather kernels ---------------------------------------------

// one warp per node; out[node] = (sum feat[src]) * dinv[node]
__global__ __launch_bounds__(256) void k_gather1(
    const float4* __restrict__ feat, const int* __restrict__ rowstart,
    const int* __restrict__ degi, const int* __restrict__ srclist,
    const float* __restrict__ dinv, float4* __restrict__ out) {
    int node = blockIdx.x * 8 + (threadIdx.x >> 5);
    if (node >= NN) return;
    int lane = threadIdx.x & 31;
    int half = lane >> 4;
    int c = lane & 15;
    int beg = rowstart[node];
    int cnt = degi[node];
    float4 acc = make_float4(0.f, 0.f, 0.f, 0.f);
    for (int i = half; i < cnt; i += 2) {
        int s = __ldg(&srclist[beg + i]);
        float4 v = __ldg(&feat[(long long)s * 16 + c]);
        acc.x += v.x; acc.y += v.y; acc.z += v.z; acc.w += v.w;
    }
    acc.x += __shfl_xor_sync(0xffffffffu, acc.x, 16);
    acc.y += __shfl_xor_sync(0xffffffffu, acc.y, 16);
    acc.z += __shfl_xor_sync(0xffffffffu, acc.z, 16);
    acc.w += __shfl_xor_sync(0xffffffffu, acc.w, 16);
    if (half == 0) {
        float di = dinv[node];
        out[(long long)node * 16 + c] =
            make_float4(acc.x * di, acc.y * di, acc.z * di, acc.w * di);
    }
}

// gather + layer2 epilogue: h2 = relu(s2 + agg(p)*dinv + b2)
__global__ __launch_bounds__(256) void k_gather2(
    const float4* __restrict__ pfeat, const int* __restrict__ rowstart,
    const int* __restrict__ degi, const int* __restrict__ srclist,
    const float* __restrict__ dinv, const float4* __restrict__ s2,
    const float4* __restrict__ b2, float4* __restrict__ h2) {
    int node = blockIdx.x * 8 + (threadIdx.x >> 5);
    if (node >= NN) return;
    int lane = threadIdx.x & 31;
    int half = lane >> 4;
    int c = lane & 15;
    int beg = rowstart[node];
    int cnt = degi[node];
    float4 acc = make_float4(0.f, 0.f, 0.f, 0.f);
    for (int i = half; i < cnt; i += 2) {
        int s = __ldg(&srclist[beg + i]);
        float4 v = __ldg(&pfeat[(long long)s * 16 + c]);
        acc.x += v.x; acc.y += v.y; acc.z += v.z; acc.w += v.w;
    }
    acc.x += __shfl_xor_sync(0xffffffffu, acc.x, 16);
    acc.y += __shfl_xor_sync(0xffffffffu, acc.y, 16);
    acc.z += __shfl_xor_sync(0xffffffffu, acc.z, 16);
    acc.w += __shfl_xor_sync(0xffffffffu, acc.w, 16);
    if (half == 0) {
        float di = dinv[node];
        float4 sv = __ldg(&s2[(long long)node * 16 + c]);
        float4 bv = __ldg(&b2[c]);
        float4 r;
        r.x = fmaxf(sv.x + acc.x * di + bv.x, 0.f);
        r.y = fmaxf(sv.y + acc.y * di + bv.y, 0.f);
        r.z = fmaxf(sv.z + acc.z * di + bv.z, 0.f);
        r.w = fmaxf(sv.w + acc.w * di + bv.w, 0.f);
        h2[(long long)node * 16 + c] = r;
    }
}

// ---------------- GEMM kernels (2D register tiling, FMA-bound) ---------------

// layer1: h1 = relu(x@Ws + agg@Wn + b). 32 nodes/block, 128 threads.
// Thread tile: 4 cols (j0 = lane*4) x 8 nodes (warp picks node group).
__global__ __launch_bounds__(128) void k_layer1(
    const float* __restrict__ x, const float* __restrict__ agg,
    const float* __restrict__ Wself, const float* __restrict__ Wneigh,
    const float* __restrict__ b, float* __restrict__ h1) {
    __shared__ float sW[INC * HIDC];   // 32 KB: [k][j] 64x128
    __shared__ float sF[32 * INC];     // 8 KB : [n][k] 32x64
    const int tid = threadIdx.x;
    const int lane = tid & 31;
    const int wrp = tid >> 5;
    const int j0 = lane * 4;
    const int nb = wrp * 8;
    const int n0 = blockIdx.x * 32;

    float4 acc[8];
#pragma unroll
    for (int n = 0; n < 8; n++) acc[n] = make_float4(0.f, 0.f, 0.f, 0.f);

#pragma unroll
    for (int pass = 0; pass < 2; pass++) {
        const float* W = pass ? Wneigh : Wself;
        const float* F = pass ? agg : x;
        if (pass) __syncthreads();
        // load weights [64][128] and features [32][64] (float4, coalesced)
        for (int i = tid; i < INC * HIDC / 4; i += 128)
            ((float4*)sW)[i] = ((const float4*)W)[i];
        {
            const float4* fr = (const float4*)(F + (long long)n0 * INC);
            for (int i = tid; i < 32 * INC / 4; i += 128) ((float4*)sF)[i] = fr[i];
        }
        __syncthreads();
#pragma unroll 4
        for (int k4 = 0; k4 < 16; k4++) {
            float4 w0 = *(const float4*)&sW[(k4 * 4 + 0) * HIDC + j0];
            float4 w1 = *(const float4*)&sW[(k4 * 4 + 1) * HIDC + j0];
            float4 w2 = *(const float4*)&sW[(k4 * 4 + 2) * HIDC + j0];
            float4 w3 = *(const float4*)&sW[(k4 * 4 + 3) * HIDC + j0];
#pragma unroll
            for (int n = 0; n < 8; n++) {
                float4 f = *(const float4*)&sF[(nb + n) * INC + k4 * 4];
                acc[n].x = fmaf(f.x, w0.x, acc[n].x);
                acc[n].y = fmaf(f.x, w0.y, acc[n].y);
                acc[n].z = fmaf(f.x, w0.z, acc[n].z);
                acc[n].w = fmaf(f.x, w0.w, acc[n].w);
                acc[n].x = fmaf(f.y, w1.x, acc[n].x);
                acc[n].y = fmaf(f.y, w1.y, acc[n].y);
                acc[n].z = fmaf(f.y, w1.z, acc[n].z);
                acc[n].w = fmaf(f.y, w1.w, acc[n].w);
                acc[n].x = fmaf(f.z, w2.x, acc[n].x);
                acc[n].y = fmaf(f.z, w2.y, acc[n].y);
                acc[n].z = fmaf(f.z, w2.z, acc[n].z);
                acc[n].w = fmaf(f.z, w2.w, acc[n].w);
                acc[n].x = fmaf(f.w, w3.x, acc[n].x);
                acc[n].y = fmaf(f.w, w3.y, acc[n].y);
                acc[n].z = fmaf(f.w, w3.z, acc[n].z);
                acc[n].w = fmaf(f.w, w3.w, acc[n].w);
            }
        }
    }
    float4 bv = *(const float4*)&b[j0];
#pragma unroll
    for (int n = 0; n < 8; n++) {
        float4 r;
        r.x = fmaxf(acc[n].x + bv.x, 0.f);
        r.y = fmaxf(acc[n].y + bv.y, 0.f);
        r.z = fmaxf(acc[n].z + bv.z, 0.f);
        r.w = fmaxf(acc[n].w + bv.w, 0.f);
        *(float4*)&h1[((long long)(n0 + nb + n)) * HIDC + j0] = r;
    }
}

// dual GEMM: s2 = h1@Ws2, p = h1@Wn2. 128 virtual cols = [S 0..63 | P 64..127].
// K=128 in two 64-k passes. 32 nodes/block, 128 threads, 4 cols x 8 nodes tile.
__global__ __launch_bounds__(128) void k_dual(
    const float* __restrict__ h1,
    const float* __restrict__ Wself2, const float* __restrict__ Wneigh2,
    float* __restrict__ s2, float* __restrict__ p) {
    __shared__ float sW[64 * 128];     // 32 KB: [kk][jv] for current k-slice
    __shared__ float sF[32 * 64];      // 8 KB : [n][kk]
    const int tid = threadIdx.x;
    const int lane = tid & 31;
    const int wrp = tid >> 5;
    const int j0 = lane * 4;           // virtual col (all 4 in same matrix)
    const int nb = wrp * 8;
    const int n0 = blockIdx.x * 32;

    float4 acc[8];
#pragma unroll
    for (int n = 0; n < 8; n++) acc[n] = make_float4(0.f, 0.f, 0.f, 0.f);

#pragma unroll
    for (int kp = 0; kp < 2; kp++) {
        if (kp) __syncthreads();
        // sW[kk*128 + jv]: jv<64 -> Ws2[kp*64+kk][jv], else Wn2[kp*64+kk][jv-64]
        for (int i = tid * 4; i < 64 * 128; i += 128 * 4) {
            int kk = i >> 7, jv = i & 127;
            const float* W = (jv < 64) ? Wself2 : Wneigh2;
            *(float4*)&sW[i] = *(const float4*)&W[(kp * 64 + kk) * OUTC + (jv & 63)];
        }
        // sF[n*64 + kk] = h1[(n0+n)*128 + kp*64 + kk]
        for (int i = tid * 4; i < 32 * 64; i += 128 * 4) {
            int n = i >> 6, kk = i & 63;
            *(float4*)&sF[i] = *(const float4*)&h1[((long long)(n0 + n)) * HIDC + kp * 64 + kk];
        }
        __syncthreads();
#pragma unroll 4
        for (int k4 = 0; k4 < 16; k4++) {
            float4 w0 = *(const float4*)&sW[(k4 * 4 + 0) * 128 + j0];
            float4 w1 = *(const float4*)&sW[(k4 * 4 + 1) * 128 + j0];
            float4 w2 = *(const float4*)&sW[(k4 * 4 + 2) * 128 + j0];
            float4 w3 = *(const float4*)&sW[(k4 * 4 + 3) * 128 + j0];
#pragma unroll
            for (int n = 0; n < 8; n++) {
                float4 f = *(const float4*)&sF[(nb + n) * 64 + k4 * 4];
                acc[n].x = fmaf(f.x, w0.x, acc[n].x);
                acc[n].y = fmaf(f.x, w0.y, acc[n].y);
                acc[n].z = fmaf(f.x, w0.z, acc[n].z);
                acc[n].w = fmaf(f.x, w0.w, acc[n].w);
                acc[n].x = fmaf(f.y, w1.x, acc[n].x);
                acc[n].y = fmaf(f.y, w1.y, acc[n].y);
                acc[n].z = fmaf(f.y, w1.z, acc[n].z);
                acc[n].w = fmaf(f.y, w1.w, acc[n].w);
                acc[n].x = fmaf(f.z, w2.x, acc[n].x);
                acc[n].y = fmaf(f.z, w2.y, acc[n].y);
                acc[n].z = fmaf(f.z, w2.z, acc[n].z);
                acc[n].w = fmaf(f.z, w2.w, acc[n].w);
                acc[n].x = fmaf(f.w, w3.x, acc[n].x);
                acc[n].y = fmaf(f.w, w3.y, acc[n].y);
                acc[n].z = fmaf(f.w, w3.z, acc[n].z);
                acc[n].w = fmaf(f.w, w3.w, acc[n].w);
            }
        }
    }
    float* dst = (j0 < 64) ? s2 : p;
    int jd = j0 & 63;
#pragma unroll
    for (int n = 0; n < 8; n++)
        *(float4*)&dst[((long long)(n0 + nb + n)) * OUTC + jd] = acc[n];
}

// classifier: out = h2 @ wc + bc
__global__ __launch_bounds__(256) void k_out(const float* __restrict__ h2,
                                             const float* __restrict__ wc,
                                             const float* __restrict__ bc,
                                             float* __restrict__ out) {
    __shared__ float sW[OUTC * NCLS];
    __shared__ float sB[NCLS];
    __shared__ float sH[12 * 65];
    const int tid = threadIdx.x;
    const int n0 = blockIdx.x * 12;
    const int nmax = min(12, NN - n0);
    for (int i = tid; i < OUTC * NCLS; i += 256) sW[i] = wc[i];
    if (tid < NCLS) sB[tid] = bc[tid];
    for (int i = tid; i < nmax * OUTC; i += 256) {
        int ln = i >> 6, k = i & 63;
        sH[ln * 65 + k] = h2[(long long)(n0 + ln) * OUTC + k];
    }
    __syncthreads();
    if (tid < 240) {
        int ln = tid / 20, c = tid % 20;
        if (ln < nmax) {
            float acc = sB[c];
#pragma unroll
            for (int k = 0; k < OUTC; k++)
                acc = fmaf(sH[ln * 65 + k], sW[k * NCLS + c], acc);
            out[(long long)(n0 + ln) * NCLS + c] = acc;
        }
    }
}

// ---------------- launch ----------------------------------------------------
extern "C" void kernel_launch(void* const* d_in, const int* in_sizes, int n_in,
                              void* d_out, int out_size) {
    const float* x   = (const float*)d_in[0];
    const void*  ei  = d_in[1];
    const float* ws1 = (const float*)d_in[2];
    const float* wn1 = (const float*)d_in[3];
    const float* b1  = (const float*)d_in[4];
    const float* ws2 = (const float*)d_in[5];
    const float* wn2 = (const float*)d_in[6];
    const float* b2  = (const float*)d_in[7];
    const float* wc  = (const float*)d_in[8];
    const float* bc  = (const float*)d_in[9];
    float* out = (float*)d_out;

    int nE = in_sizes[1] / 2;
    if (nE > NE_MAX) nE = NE_MAX;

    void *p_flag, *p_edges, *p_degi, *p_rs, *p_cur, *p_src, *p_cs, *p_co;
    void *p_dinv, *p_agg1, *p_h1, *p_pp, *p_s2, *p_h2;
    cudaGetSymbolAddress(&p_flag, g_is64);
    cudaGetSymbolAddress(&p_edges, g_edges);
    cudaGetSymbolAddress(&p_degi, g_degi);
    cudaGetSymbolAddress(&p_rs,   g_rowstart);
    cudaGetSymbolAddress(&p_cur,  g_cursor);
    cudaGetSymbolAddress(&p_src,  g_srclist);
    cudaGetSymbolAddress(&p_cs,   g_chunksum);
    cudaGetSymbolAddress(&p_co,   g_chunkoff);
    cudaGetSymbolAddress(&p_dinv, g_dinv);
    cudaGetSymbolAddress(&p_agg1, g_agg1);
    cudaGetSymbolAddress(&p_h1,   g_h1);
    cudaGetSymbolAddress(&p_pp,   g_p);
    cudaGetSymbolAddress(&p_s2,   g_s2);
    cudaGetSymbolAddress(&p_h2,   g_h2);
    int*   flag  = (int*)p_flag;
    int2*  edges = (int2*)p_edges;
    int*   degi  = (int*)p_degi;
    int*   rs    = (int*)p_rs;
    int*   cur   = (int*)p_cur;
    int*   src   = (int*)p_src;
    int*   cs    = (int*)p_cs;
    int*   co    = (int*)p_co;
    float* dinv  = (float*)p_dinv;
    float* agg1  = (float*)p_agg1;
    float* h1    = (float*)p_h1;
    float* pp    = (float*)p_pp;
    float* s2    = (float*)p_s2;
    float* h2    = (float*)p_h2;

    // dtype detect + CSR build
    k_detect<<<1, 256>>>((const int*)ei, in_sizes[1], flag);
    k_zero_deg<<<(NN + 255) / 256, 256>>>(degi);
    k_convert<<<(nE + 255) / 256, 256>>>(ei, nE, edges, degi, flag);
    k_scanA<<<NCHUNK, 1024>>>(degi, cs);
    k_scanB<<<1, 128>>>(cs, co);
    k_scanC<<<NCHUNK, 1024>>>(degi, co, rs, cur, dinv);
    k_scatter<<<(nE + 255) / 256, 256>>>(edges, nE, cur, src);

    // layer 1
    k_gather1<<<(NN + 7) / 8, 256>>>((const float4*)x, rs, degi, src, dinv,
                                     (float4*)agg1);
    k_layer1<<<NN / 32, 128>>>(x, agg1, ws1, wn1, b1, h1);

    // layer 2
    k_dual<<<NN / 32, 128>>>(h1, ws2, wn2, s2, pp);
    k_gather2<<<(NN + 7) / 8, 256>>>((const float4*)pp, rs, degi, src, dinv,
                                     (const float4*)s2, (const float4*)b2,
                                     (float4*)h2);

    // classifier
    k_out<<<(NN + 11) / 12, 256>>>(h2, wc, bc, out);
}